// round 16
// baseline (speedup 1.0000x reference)
#include <cuda_runtime.h>
#include <cuda_bf16.h>
#include <cstdint>

#define NN 100000
#define EE 800000
#define HH 128
#define BB 64
#define NB1 196   // ceil(NN/512)

// ---------------- scratch (device globals: no runtime allocation) ----------------
// NOTE: g_deg relies on zero-init at module load; k_fill re-zeroes it every call.
__device__ __nv_bfloat162 g_ub[(size_t)NN * 64]; // bf16 u (gather input + head path)
__device__ uint2 g_meanb[(size_t)NN * 32];       // bf16 seg-mean rows (mma A input)
__device__ __nv_bfloat16 g_wtb[2 * HH * HH];     // bf16 W^T for hops 1,2  [c][k]
__device__ float g_third[NN];                    // seg_mean(ee) per node (per hop)
__device__ int   g_deg[NN];
__device__ int   g_start[NN + 1];
__device__ int   g_cursor[NN];
__device__ int   g_bsum[NB1 + 4];
__device__ int2  g_edge[EE];                     // packed (col, ea-bits) per CSR slot
__device__ float g_v0t[BB * HH], g_v1t[BB * HH];
__device__ float g_scal[BB * 10];                // s0,s1,p0,p1,a0,a1,d00,d01,d10,d11
__device__ float g_spvec[HH], g_actop[HH], g_acbot[HH];
__device__ float g_c0;

__device__ __forceinline__ uint32_t smem_u32(const void* p) {
    uint32_t a;
    asm("{ .reg .u64 t; cvta.to.shared.u64 t, %1; cvt.u32.u64 %0, t; }" : "=r"(a) : "l"(p));
    return a;
}

// smem layout for k_hmma (bf16, rows padded to 136 elems = 272 B)
#define ASTB 136
#define SH_A 0
#define SH_B (128 * ASTB * 2)            // 34816
#define SH_CB (2 * 128 * ASTB * 2)       // 69632
#define SH_C0 (SH_CB + 512)
#define SH_C2 (SH_C0 + 512)
#define SH_TOTAL (SH_C2 + 512)           // 71168

// ---------------- hist + (spread) W^T bf16 + (block 0) folded head vectors ----------------
__global__ void k_hist(const int* __restrict__ row, const float* __restrict__ l1w,
                       const float* __restrict__ spw, const float* __restrict__ spb,
                       const float* __restrict__ acw, const float* __restrict__ acb,
                       const float* __restrict__ lastw, const float* __restrict__ lastb) {
    int e = blockIdx.x * blockDim.x + threadIdx.x;
    if (e < EE) atomicAdd(&g_deg[row[e]], 1);
    // W^T -> bf16 spread over first 128 blocks: g_wtb[(hop-1)][c][k] = bf16(W[hop][k][c])
    if (blockIdx.x < 128) {
        int i = blockIdx.x * 256 + threadIdx.x;   // < 32768 = 2*128*128
        int hop = i >> 14;
        int c = (i >> 7) & 127;
        int k = i & 127;
        g_wtb[i] = __float2bfloat16(l1w[(hop + 1) * HH * HH + k * HH + c]);
    }
    if (blockIdx.x == 0) {
        int t = threadIdx.x;  // 256
        if (t < HH) {
            float s = 0.f;
            for (int j = 0; j < HH; j++) s += spw[t * HH + j] * lastw[j];
            g_spvec[t] = s;
        }
        {
            float s = 0.f;
            for (int j = 0; j < HH; j++) s += acw[t * HH + j] * lastw[HH + j];
            if (t < HH) g_actop[t] = s; else g_acbot[t - HH] = s;
        }
        if (t < 32) {
            float s = 0.f;
            for (int j = t; j < HH; j += 32) s += spb[j] * lastw[j] + acb[j] * lastw[HH + j];
            for (int o = 16; o; o >>= 1) s += __shfl_down_sync(0xffffffffu, s, o);
            if (t == 0) g_c0 = s + lastb[0];
        }
    }
}

// ---- scan ----
__global__ void k_scan1() {
    int t = threadIdx.x;                     // 256 threads, 512 nodes/block
    int n0 = blockIdx.x * 512;
    int s = 0;
    int i = n0 + t;
    if (i < NN) s += g_deg[i];
    if (i + 256 < n0 + 512 && i + 256 < NN) s += g_deg[i + 256];
    int lane = t & 31, warp = t >> 5;
    for (int o = 16; o; o >>= 1) s += __shfl_down_sync(0xffffffffu, s, o);
    __shared__ int ws[8];
    if (lane == 0) ws[warp] = s;
    __syncthreads();
    if (t == 0) {
        int tot = 0;
        #pragma unroll
        for (int w = 0; w < 8; w++) tot += ws[w];
        g_bsum[blockIdx.x] = tot;
    }
}

__global__ void k_scan3() {
    int t = threadIdx.x, blk = blockIdx.x;   // 256 threads
    __shared__ int ws[8], wo[8], sBoff;
    int lane = t & 31, warp = t >> 5;

    int bv = (t < blk) ? g_bsum[t] : 0;
    for (int o = 16; o; o >>= 1) bv += __shfl_down_sync(0xffffffffu, bv, o);
    if (lane == 0) ws[warp] = bv;
    __syncthreads();
    if (t == 0) {
        int tot = 0;
        #pragma unroll
        for (int w = 0; w < 8; w++) tot += ws[w];
        sBoff = tot;
    }
    __syncthreads();

    int i0 = blk * 512 + t * 2;
    int d0 = (i0 < NN) ? g_deg[i0] : 0;
    int d1 = (i0 + 1 < NN) ? g_deg[i0 + 1] : 0;
    int s = d0 + d1;
    int v = s;
    for (int o = 1; o < 32; o <<= 1) {
        int u = __shfl_up_sync(0xffffffffu, v, o);
        if (lane >= o) v += u;
    }
    if (lane == 31) ws[warp] = v;
    __syncthreads();
    if (t == 0) {
        int run = 0;
        #pragma unroll
        for (int w = 0; w < 8; w++) { wo[w] = run; run += ws[w]; }
    }
    __syncthreads();
    int ex = v - s + wo[warp] + sBoff;
    if (i0 < NN)     { g_start[i0] = ex;          g_cursor[i0] = ex; }
    if (i0 + 1 < NN) { g_start[i0 + 1] = ex + d0; g_cursor[i0 + 1] = ex + d0; }
    if (i0 == NN)    { g_start[NN] = ex; }   // ex == EE at i0 == NN
}

// fill CSR (packed edges) + re-zero g_deg (dead after scan3; restores call invariant)
__global__ void k_fill(const int* __restrict__ row, const int* __restrict__ col,
                       const float* __restrict__ ea) {
    int e = blockIdx.x * blockDim.x + threadIdx.x;
    if (e < NN) g_deg[e] = 0;
    if (e >= EE) return;
    int r = row[e];
    int idx = atomicAdd(&g_cursor[r], 1);
    int2 pk;
    pk.x = col[e];
    pk.y = __float_as_int(ea[e]);
    g_edge[idx] = pk;
}

// hop 0 fused (u==0): warp per node; lanes split edges for third term; emit bf16 u.
__global__ void k_hop0(const float* __restrict__ x,
                       const float* __restrict__ l3w, const float* __restrict__ l3b,
                       const float* __restrict__ l0w, const float* __restrict__ l0b,
                       const float* __restrict__ l1b,
                       const float* __restrict__ l2w, const float* __restrict__ l2b) {
    int warp = threadIdx.x >> 5, lane = threadIdx.x & 31;
    int n = blockIdx.x * 8 + warp;
    if (n >= NN) return;
    float w = l3w[0], b = l3b[0];
    int s = g_start[n], e = g_start[n + 1];
    float acc = 0.f;
    for (int t = s + lane; t < e; t += 32)
        acc += fmaxf(__int_as_float(g_edge[t].y) * w + b, 0.f);
    for (int o = 16; o; o >>= 1) acc += __shfl_xor_sync(0xffffffffu, acc, o);
    float third = (e > s) ? acc / (float)(e - s) : 0.f;
    float xv = x[n];
    int h0 = lane * 4;
    float v0 = xv * l0w[h0]     + third * l2w[h0]     + l0b[h0]     + l1b[h0]     + l2b[h0];
    float v1 = xv * l0w[h0 + 1] + third * l2w[h0 + 1] + l0b[h0 + 1] + l1b[h0 + 1] + l2b[h0 + 1];
    float v2 = xv * l0w[h0 + 2] + third * l2w[h0 + 2] + l0b[h0 + 2] + l1b[h0 + 2] + l2b[h0 + 2];
    float v3 = xv * l0w[h0 + 3] + third * l2w[h0 + 3] + l0b[h0 + 3] + l1b[h0 + 3] + l2b[h0 + 3];
    __nv_bfloat162 lo = __floats2bfloat162_rn(fmaxf(v0, 0.f), fmaxf(v1, 0.f));
    __nv_bfloat162 hi = __floats2bfloat162_rn(fmaxf(v2, 0.f), fmaxf(v3, 0.f));
    uint2 pk;
    pk.x = *reinterpret_cast<unsigned*>(&lo);
    pk.y = *reinterpret_cast<unsigned*>(&hi);
    reinterpret_cast<uint2*>(g_ub)[(size_t)n * 32 + lane] = pk;
}

// edge aggregation: 2 nodes per warp (16 lanes each, uint4 = 8 bf16 per lane).
// Packed edge stream; bf16 mean out; full-third per lane, hl==0 writes it.
__global__ void k_gather(const float* __restrict__ l3w, const float* __restrict__ l3b) {
    int warp = threadIdx.x >> 5, lane = threadIdx.x & 31;
    int hl = lane & 15;                      // lane within half-warp
    int n = blockIdx.x * 16 + warp * 2 + (lane >> 4);
    if (n >= NN) return;
    const uint4* ub4 = reinterpret_cast<const uint4*>(g_ub);  // 16 uint4 per node row
    float w = l3w[0], b = l3b[0];
    int s = g_start[n], e = g_start[n + 1];
    float a0x = 0.f, a1x = 0.f, a2x = 0.f, a3x = 0.f;
    float a4x = 0.f, a5x = 0.f, a6x = 0.f, a7x = 0.f;
    float tacc = 0.f;
    int t = s;
    for (; t + 3 < e; t += 4) {
        int2 e0 = g_edge[t],     e1 = g_edge[t + 1];
        int2 e2 = g_edge[t + 2], e3 = g_edge[t + 3];
        float c0 = __int_as_float(e0.y), c1 = __int_as_float(e1.y);
        float c2 = __int_as_float(e2.y), c3 = __int_as_float(e3.y);
        uint4 r0 = ub4[(size_t)e0.x * 16 + hl];
        uint4 r1 = ub4[(size_t)e1.x * 16 + hl];
        uint4 r2 = ub4[(size_t)e2.x * 16 + hl];
        uint4 r3 = ub4[(size_t)e3.x * 16 + hl];
        #define ACC8(R, C) { \
            float2 f0 = __bfloat1622float2(*reinterpret_cast<__nv_bfloat162*>(&R.x)); \
            float2 f1 = __bfloat1622float2(*reinterpret_cast<__nv_bfloat162*>(&R.y)); \
            float2 f2 = __bfloat1622float2(*reinterpret_cast<__nv_bfloat162*>(&R.z)); \
            float2 f3 = __bfloat1622float2(*reinterpret_cast<__nv_bfloat162*>(&R.w)); \
            a0x += C * f0.x; a1x += C * f0.y; a2x += C * f1.x; a3x += C * f1.y; \
            a4x += C * f2.x; a5x += C * f2.y; a6x += C * f3.x; a7x += C * f3.y; }
        ACC8(r0, c0) ACC8(r1, c1) ACC8(r2, c2) ACC8(r3, c3)
        tacc += fmaxf(c0 * w + b, 0.f) + fmaxf(c1 * w + b, 0.f)
              + fmaxf(c2 * w + b, 0.f) + fmaxf(c3 * w + b, 0.f);
    }
    for (; t < e; t++) {
        int2 e0 = g_edge[t];
        float c0 = __int_as_float(e0.y);
        uint4 r0 = ub4[(size_t)e0.x * 16 + hl];
        ACC8(r0, c0)
        tacc += fmaxf(c0 * w + b, 0.f);
    }
    #undef ACC8
    float inv = (e > s) ? 1.f / (float)(e - s) : 0.f;
    __nv_bfloat162 b0 = __floats2bfloat162_rn(a0x * inv, a1x * inv);
    __nv_bfloat162 b1 = __floats2bfloat162_rn(a2x * inv, a3x * inv);
    __nv_bfloat162 b2 = __floats2bfloat162_rn(a4x * inv, a5x * inv);
    __nv_bfloat162 b3 = __floats2bfloat162_rn(a6x * inv, a7x * inv);
    uint4 pk;
    pk.x = *reinterpret_cast<unsigned*>(&b0);
    pk.y = *reinterpret_cast<unsigned*>(&b1);
    pk.z = *reinterpret_cast<unsigned*>(&b2);
    pk.w = *reinterpret_cast<unsigned*>(&b3);
    reinterpret_cast<uint4*>(g_meanb)[(size_t)n * 16 + hl] = pk;
    if (hl == 0) g_third[n] = tacc * inv;
}

// bf16 tensor-core GEMM via mma.sync (base sm_103 ISA) + fused hop epilogue.
__global__ __launch_bounds__(256) void k_hmma(
    const float* __restrict__ x,
    const __nv_bfloat16* __restrict__ wtb,   // [128 c][128 k] bf16 row-major
    const float* __restrict__ l0w, const float* __restrict__ l2w,
    const float* __restrict__ b0, const float* __restrict__ b1,
    const float* __restrict__ b2) {
    extern __shared__ char smem[];
    uint32_t sbase = smem_u32(smem);
    int tid = threadIdx.x, lane = tid & 31, w = tid >> 5;
    int n0g = blockIdx.x * 128;

    for (int i = tid; i < 128 * 32; i += 256) {
        int row = i >> 5, u2 = i & 31;
        int n = n0g + row;
        uint2 v = (n < NN) ? g_meanb[(size_t)n * 32 + u2] : make_uint2(0u, 0u);
        *reinterpret_cast<uint2*>(smem + SH_A + row * (ASTB * 2) + u2 * 8) = v;
    }
    const uint2* wb = reinterpret_cast<const uint2*>(wtb);
    for (int i = tid; i < 128 * 32; i += 256) {
        int row = i >> 5, u2 = i & 31;
        *reinterpret_cast<uint2*>(smem + SH_B + row * (ASTB * 2) + u2 * 8) = wb[row * 32 + u2];
    }
    if (tid < 128) {
        reinterpret_cast<float*>(smem + SH_CB)[tid] = b0[tid] + b1[tid] + b2[tid];
        reinterpret_cast<float*>(smem + SH_C0)[tid] = l0w[tid];
        reinterpret_cast<float*>(smem + SH_C2)[tid] = l2w[tid];
    }
    __syncthreads();

    int lg = lane >> 3, li = lane & 7;
    int rowA = w * 16 + (lg & 1) * 8 + li;
    uint32_t aBase = sbase + SH_A + rowA * (ASTB * 2) + ((lg >> 1) * 8) * 2;
    int rowBb = (lg >> 1) * 8 + li;
    uint32_t bBase = sbase + SH_B + rowBb * (ASTB * 2) + ((lg & 1) * 8) * 2;

    float acc[16][4];
    #pragma unroll
    for (int t = 0; t < 16; t++)
        #pragma unroll
        for (int j = 0; j < 4; j++) acc[t][j] = 0.f;

    #pragma unroll 1
    for (int ks = 0; ks < 8; ks++) {
        uint32_t kb2 = ks * 32;
        uint32_t a0, a1, a2, a3;
        asm volatile("ldmatrix.sync.aligned.m8n8.x4.shared.b16 {%0,%1,%2,%3}, [%4];"
                     : "=r"(a0), "=r"(a1), "=r"(a2), "=r"(a3) : "r"(aBase + kb2));
        #pragma unroll
        for (int np = 0; np < 8; np++) {
            uint32_t r0, r1, r2, r3;
            asm volatile("ldmatrix.sync.aligned.m8n8.x4.shared.b16 {%0,%1,%2,%3}, [%4];"
                         : "=r"(r0), "=r"(r1), "=r"(r2), "=r"(r3)
                         : "r"(bBase + np * 16 * (ASTB * 2) + kb2));
            asm volatile(
                "mma.sync.aligned.m16n8k16.row.col.f32.bf16.bf16.f32 "
                "{%0,%1,%2,%3}, {%4,%5,%6,%7}, {%8,%9}, {%0,%1,%2,%3};"
                : "+f"(acc[2 * np][0]), "+f"(acc[2 * np][1]),
                  "+f"(acc[2 * np][2]), "+f"(acc[2 * np][3])
                : "r"(a0), "r"(a1), "r"(a2), "r"(a3), "r"(r0), "r"(r1));
            asm volatile(
                "mma.sync.aligned.m16n8k16.row.col.f32.bf16.bf16.f32 "
                "{%0,%1,%2,%3}, {%4,%5,%6,%7}, {%8,%9}, {%0,%1,%2,%3};"
                : "+f"(acc[2 * np + 1][0]), "+f"(acc[2 * np + 1][1]),
                  "+f"(acc[2 * np + 1][2]), "+f"(acc[2 * np + 1][3])
                : "r"(a0), "r"(a1), "r"(a2), "r"(a3), "r"(r2), "r"(r3));
        }
    }

    int q = lane & 3;
    int row0 = w * 16 + (lane >> 2), row1 = row0 + 8;
    int nA = n0g + row0, nB = n0g + row1;
    float xA = 0.f, tA = 0.f, xB = 0.f, tB = 0.f;
    if (nA < NN) { xA = x[nA]; tA = g_third[nA]; }
    if (nB < NN) { xB = x[nB]; tB = g_third[nB]; }
    const float* sCB = reinterpret_cast<const float*>(smem + SH_CB);
    const float* sC0 = reinterpret_cast<const float*>(smem + SH_C0);
    const float* sC2 = reinterpret_cast<const float*>(smem + SH_C2);

    #pragma unroll
    for (int t = 0; t < 16; t++) {
        int c = t * 8 + q * 2;
        float2 bb = *reinterpret_cast<const float2*>(&sCB[c]);
        float2 w0 = *reinterpret_cast<const float2*>(&sC0[c]);
        float2 w2 = *reinterpret_cast<const float2*>(&sC2[c]);
        float oA0 = fmaxf(xA * w0.x + tA * w2.x + bb.x + acc[t][0], 0.f);
        float oA1 = fmaxf(xA * w0.y + tA * w2.y + bb.y + acc[t][1], 0.f);
        float oB0 = fmaxf(xB * w0.x + tB * w2.x + bb.x + acc[t][2], 0.f);
        float oB1 = fmaxf(xB * w0.y + tB * w2.y + bb.y + acc[t][3], 0.f);
        if (nA < NN) g_ub[(size_t)nA * 64 + (c >> 1)] = __floats2bfloat162_rn(oA0, oA1);
        if (nB < NN) g_ub[(size_t)nB * 64 + (c >> 1)] = __floats2bfloat162_rn(oB0, oB1);
    }
}

__device__ __forceinline__ int lbound(const int* __restrict__ batch, int key) {
    int lo = 0, hi = NN;
    while (lo < hi) {
        int mid = (lo + hi) >> 1;
        if (batch[mid] < key) lo = mid + 1; else hi = mid;
    }
    return lo;
}

// merged pool+graph: block g sums its own node range (batch sorted; binary search),
// builds hc0/hc1, folded attention vectors v0/v1 = att_w @ hc, and 10 scalars.
__global__ void k_pg(const float* __restrict__ x, const int* __restrict__ batch,
                     const float* __restrict__ attw, const float* __restrict__ attb) {
    __shared__ float s0[2][HH], s1[2][HH], scnt[2][2];
    __shared__ float hc0[HH], hc1[HH], v0[2 * HH], v1[2 * HH];
    int g = blockIdx.x, t = threadIdx.x;  // 256 threads
    int half = t >> 7, h = t & 127;
    int nA = lbound(batch, g), nB = lbound(batch, g + 1);
    int mid = (nA + nB) >> 1;
    int lo = half ? mid : nA, hiN = half ? nB : mid;
    const __nv_bfloat16* ubh = reinterpret_cast<const __nv_bfloat16*>(g_ub);
    float a0 = 0.f, a1 = 0.f, c0 = 0.f, c1 = 0.f;
    for (int n = lo; n < hiN; n++) {
        float xv = x[n];
        float uv = __bfloat162float(ubh[(size_t)n * HH + h]);
        a0 += uv * (1.f - xv); a1 += uv * xv;
        c0 += 1.f - xv;        c1 += xv;
    }
    s0[half][h] = a0; s1[half][h] = a1;
    if (h == 0) { scnt[half][0] = c0; scnt[half][1] = c1; }
    __syncthreads();
    if (t < HH) {
        float cnt0 = scnt[0][0] + scnt[1][0];
        float cnt1 = scnt[0][1] + scnt[1][1];
        float ss0 = s0[0][t] + s0[1][t];
        float ss1 = s1[0][t] + s1[1][t];
        hc0[t] = (cnt0 > 0.f) ? ss0 / cnt0 : 0.f;
        hc1[t] = (cnt1 > 0.f) ? ss1 / cnt1 : 0.f;
    }
    __syncthreads();
    {
        float sA = 0.f, sB = 0.f;
        const float* wrow = attw + t * HH;
        for (int j = 0; j < HH; j++) { float w = wrow[j]; sA += w * hc0[j]; sB += w * hc1[j]; }
        v0[t] = sA; v1[t] = sB;
        if (t < HH) { g_v0t[g * HH + t] = sA; g_v1t[g * HH + t] = sB; }
    }
    __syncthreads();
    int warp = t >> 5, lane = t & 31;
    for (int id = warp; id < 10; id += 8) {
        const float* vec; const float* hc;
        switch (id) {
            case 0: vec = attb;     hc = hc0; break;  // s0
            case 1: vec = attb;     hc = hc1; break;  // s1
            case 2: vec = g_spvec;  hc = hc0; break;  // p0
            case 3: vec = g_spvec;  hc = hc1; break;  // p1
            case 4: vec = g_acbot;  hc = hc0; break;  // a0
            case 5: vec = g_acbot;  hc = hc1; break;  // a1
            case 6: vec = v0 + HH;  hc = hc0; break;  // d00
            case 7: vec = v0 + HH;  hc = hc1; break;  // d01
            case 8: vec = v1 + HH;  hc = hc0; break;  // d10
            default: vec = v1 + HH; hc = hc1; break;  // d11
        }
        float s = 0.f;
        for (int j = lane; j < HH; j += 32) s += vec[j] * hc[j];
        for (int o = 16; o; o >>= 1) s += __shfl_down_sync(0xffffffffu, s, o);
        if (lane == 0) g_scal[g * 10 + id] = s;
    }
}

// per-node head: 3 dots of length 128 + softmax over 2 + folded output (bf16 u)
__global__ void k_final(const float* __restrict__ x, const int* __restrict__ batch,
                        float* __restrict__ out) {
    int warp = threadIdx.x >> 5, lane = threadIdx.x & 31;
    int n = blockIdx.x * 8 + warp;
    if (n >= NN) return;
    int g = batch[n];
    uint2 upk = reinterpret_cast<const uint2*>(g_ub)[(size_t)n * 32 + lane];
    float2 ulo = __bfloat1622float2(*reinterpret_cast<__nv_bfloat162*>(&upk.x));
    float2 uhi = __bfloat1622float2(*reinterpret_cast<__nv_bfloat162*>(&upk.y));
    float4 uv = make_float4(ulo.x, ulo.y, uhi.x, uhi.y);
    float4 vA = *reinterpret_cast<const float4*>(&g_v0t[g * HH + lane * 4]);
    float4 vB = *reinterpret_cast<const float4*>(&g_v1t[g * HH + lane * 4]);
    float4 vC = *reinterpret_cast<const float4*>(&g_actop[lane * 4]);
    float da = uv.x * vA.x + uv.y * vA.y + uv.z * vA.z + uv.w * vA.w;
    float db = uv.x * vB.x + uv.y * vB.y + uv.z * vB.z + uv.w * vB.w;
    float dc = uv.x * vC.x + uv.y * vC.y + uv.z * vC.z + uv.w * vC.w;
    for (int o = 16; o; o >>= 1) {
        da += __shfl_down_sync(0xffffffffu, da, o);
        db += __shfl_down_sync(0xffffffffu, db, o);
        dc += __shfl_down_sync(0xffffffffu, dc, o);
    }
    if (lane == 0) {
        const float* sc = &g_scal[g * 10];
        bool xb = x[n] > 0.5f;
        float w0 = da + (xb ? sc[6] : sc[7]) + sc[0];
        float w1 = db + (xb ? sc[8] : sc[9]) + sc[1];
        float m = fmaxf(w0, w1);
        float e0 = __expf(w0 - m), e1 = __expf(w1 - m);
        float sw = e0 / (e0 + e1);
        out[n] = sw * sc[2] + (1.f - sw) * sc[3] + dc + (xb ? sc[4] : sc[5]) + g_c0;
    }
}

// ---------------- launch ----------------
extern "C" void kernel_launch(void* const* d_in, const int* in_sizes, int n_in,
                              void* d_out, int out_size) {
    int base = (n_in >= 21) ? 5 : 4;
    const float* x     = (const float*)d_in[0];
    const int*   ei    = (const int*)d_in[1];
    const float* ea    = (const float*)d_in[2];
    const int*   batch = (const int*)d_in[3];
    const float* l0w   = (const float*)d_in[base + 0];
    const float* l0b   = (const float*)d_in[base + 1];
    const float* l1w   = (const float*)d_in[base + 2];
    const float* l1b   = (const float*)d_in[base + 3];
    const float* l2w   = (const float*)d_in[base + 4];
    const float* l2b   = (const float*)d_in[base + 5];
    const float* l3w   = (const float*)d_in[base + 6];
    const float* l3b   = (const float*)d_in[base + 7];
    const float* attw  = (const float*)d_in[base + 8];
    const float* attb  = (const float*)d_in[base + 9];
    const float* spw   = (const float*)d_in[base + 10];
    const float* spb   = (const float*)d_in[base + 11];
    const float* acw   = (const float*)d_in[base + 12];
    const float* acb   = (const float*)d_in[base + 13];
    const float* lastw = (const float*)d_in[base + 14];
    const float* lastb = (const float*)d_in[base + 15];
    const int* row = ei;
    const int* col = ei + EE;
    float* out = (float*)d_out;

    static __nv_bfloat16* wtb_dev = nullptr;
    if (!wtb_dev) cudaGetSymbolAddress((void**)&wtb_dev, g_wtb);

    cudaFuncSetAttribute(k_hmma, cudaFuncAttributeMaxDynamicSharedMemorySize, SH_TOTAL);

    k_hist<<<(EE + 255) / 256, 256>>>(row, l1w, spw, spb, acw, acb, lastw, lastb);
    k_scan1<<<NB1, 256>>>();
    k_scan3<<<NB1, 256>>>();
    k_fill<<<(EE + 255) / 256, 256>>>(row, col, ea);

    // hop 0 (u == 0): fused third+update, bf16 out
    k_hop0<<<(NN + 7) / 8, 256>>>(x, l3w, l3b, l0w, l0b, l1b, l2w, l2b);

    // hops 1, 2: gather then tensor-core GEMM (bf16 u out)
    for (int i = 1; i < 3; i++) {
        k_gather<<<(NN + 15) / 16, 256>>>(l3w + i, l3b + i);
        k_hmma<<<(NN + 127) / 128, 256, SH_TOTAL>>>(
            x, wtb_dev + (i - 1) * HH * HH,
            l0w + i * HH, l2w + i * HH,
            l0b + i * HH, l1b + i * HH, l2b + i * HH);
    }

    k_pg<<<BB, 256>>>(x, batch, attw, attb);
    k_final<<<NN / 8, 256>>>(x, batch, out);
}

// round 17
// speedup vs baseline: 1.1017x; 1.1017x over previous
#include <cuda_runtime.h>
#include <cuda_bf16.h>
#include <cstdint>

#define NN 100000
#define EE 800000
#define HH 128
#define BB 64
#define NB1 196   // ceil(NN/512)

// ---------------- scratch (device globals: no runtime allocation) ----------------
// g_deg / g_gs* / g_cnt rely on zero-init at module load; k_fill re-zeroes them
// every call (they are dead by the time k_fill runs), keeping calls deterministic.
__device__ __nv_bfloat162 g_ub[(size_t)NN * 64]; // bf16 u (gather input + head path)
__device__ uint2 g_meanb[(size_t)NN * 32];       // bf16 seg-mean rows (mma A input)
__device__ __nv_bfloat16 g_wtb[2 * HH * HH];     // bf16 W^T for hops 1,2  [c][k]
__device__ float g_third[NN];                    // seg_mean(ee) per node (per hop)
__device__ int   g_deg[NN];
__device__ int   g_start[NN + 1];
__device__ int   g_cursor[NN];
__device__ int   g_bsum[NB1 + 4];
__device__ int2  g_edge[EE];                     // packed (col, ea-bits) per CSR slot
__device__ float g_gs0[BB * HH], g_gs1[BB * HH];
__device__ float g_cnt[2 * BB];
__device__ float g_v0t[BB * HH], g_v1t[BB * HH];
__device__ float g_scal[BB * 10];                // s0,s1,p0,p1,a0,a1,d00,d01,d10,d11
__device__ float g_spvec[HH], g_actop[HH], g_acbot[HH];
__device__ float g_c0;

__device__ __forceinline__ uint32_t smem_u32(const void* p) {
    uint32_t a;
    asm("{ .reg .u64 t; cvta.to.shared.u64 t, %1; cvt.u32.u64 %0, t; }" : "=r"(a) : "l"(p));
    return a;
}

// smem layout for k_hmma (bf16, rows padded to 136 elems = 272 B)
#define ASTB 136
#define SH_A 0
#define SH_B (128 * ASTB * 2)            // 34816
#define SH_CB (2 * 128 * ASTB * 2)       // 69632
#define SH_C0 (SH_CB + 512)
#define SH_C2 (SH_C0 + 512)
#define SH_TOTAL (SH_C2 + 512)           // 71168

// ---------------- hist + (spread) W^T bf16 + (block 0) folded head vectors ----------------
__global__ void k_hist(const int* __restrict__ row, const float* __restrict__ l1w,
                       const float* __restrict__ spw, const float* __restrict__ spb,
                       const float* __restrict__ acw, const float* __restrict__ acb,
                       const float* __restrict__ lastw, const float* __restrict__ lastb) {
    int e = blockIdx.x * blockDim.x + threadIdx.x;
    if (e < EE) atomicAdd(&g_deg[row[e]], 1);
    // W^T -> bf16 spread over first 128 blocks: g_wtb[(hop-1)][c][k] = bf16(W[hop][k][c])
    if (blockIdx.x < 128) {
        int i = blockIdx.x * 256 + threadIdx.x;   // < 32768 = 2*128*128
        int hop = i >> 14;
        int c = (i >> 7) & 127;
        int k = i & 127;
        g_wtb[i] = __float2bfloat16(l1w[(hop + 1) * HH * HH + k * HH + c]);
    }
    if (blockIdx.x == 0) {
        int t = threadIdx.x;  // 256
        if (t < HH) {
            float s = 0.f;
            for (int j = 0; j < HH; j++) s += spw[t * HH + j] * lastw[j];
            g_spvec[t] = s;
        }
        {
            float s = 0.f;
            for (int j = 0; j < HH; j++) s += acw[t * HH + j] * lastw[HH + j];
            if (t < HH) g_actop[t] = s; else g_acbot[t - HH] = s;
        }
        if (t < 32) {
            float s = 0.f;
            for (int j = t; j < HH; j += 32) s += spb[j] * lastw[j] + acb[j] * lastw[HH + j];
            for (int o = 16; o; o >>= 1) s += __shfl_down_sync(0xffffffffu, s, o);
            if (t == 0) g_c0 = s + lastb[0];
        }
    }
}

// ---- scan ----
__global__ void k_scan1() {
    int t = threadIdx.x;                     // 256 threads, 512 nodes/block
    int n0 = blockIdx.x * 512;
    int s = 0;
    int i = n0 + t;
    if (i < NN) s += g_deg[i];
    if (i + 256 < n0 + 512 && i + 256 < NN) s += g_deg[i + 256];
    int lane = t & 31, warp = t >> 5;
    for (int o = 16; o; o >>= 1) s += __shfl_down_sync(0xffffffffu, s, o);
    __shared__ int ws[8];
    if (lane == 0) ws[warp] = s;
    __syncthreads();
    if (t == 0) {
        int tot = 0;
        #pragma unroll
        for (int w = 0; w < 8; w++) tot += ws[w];
        g_bsum[blockIdx.x] = tot;
    }
}

__global__ void k_scan3() {
    int t = threadIdx.x, blk = blockIdx.x;   // 256 threads
    __shared__ int ws[8], wo[8], sBoff;
    int lane = t & 31, warp = t >> 5;

    int bv = (t < blk) ? g_bsum[t] : 0;
    for (int o = 16; o; o >>= 1) bv += __shfl_down_sync(0xffffffffu, bv, o);
    if (lane == 0) ws[warp] = bv;
    __syncthreads();
    if (t == 0) {
        int tot = 0;
        #pragma unroll
        for (int w = 0; w < 8; w++) tot += ws[w];
        sBoff = tot;
    }
    __syncthreads();

    int i0 = blk * 512 + t * 2;
    int d0 = (i0 < NN) ? g_deg[i0] : 0;
    int d1 = (i0 + 1 < NN) ? g_deg[i0 + 1] : 0;
    int s = d0 + d1;
    int v = s;
    for (int o = 1; o < 32; o <<= 1) {
        int u = __shfl_up_sync(0xffffffffu, v, o);
        if (lane >= o) v += u;
    }
    if (lane == 31) ws[warp] = v;
    __syncthreads();
    if (t == 0) {
        int run = 0;
        #pragma unroll
        for (int w = 0; w < 8; w++) { wo[w] = run; run += ws[w]; }
    }
    __syncthreads();
    int ex = v - s + wo[warp] + sBoff;
    if (i0 < NN)     { g_start[i0] = ex;          g_cursor[i0] = ex; }
    if (i0 + 1 < NN) { g_start[i0 + 1] = ex + d0; g_cursor[i0 + 1] = ex + d0; }
    if (i0 == NN)    { g_start[NN] = ex; }   // ex == EE at i0 == NN
}

// fill CSR (packed edges) + re-zero g_deg / pooled-sum buffers (dead here;
// restores the per-call invariant k_zero used to provide)
__global__ void k_fill(const int* __restrict__ row, const int* __restrict__ col,
                       const float* __restrict__ ea) {
    int e = blockIdx.x * blockDim.x + threadIdx.x;
    if (e < NN) g_deg[e] = 0;
    if (e < BB * HH) { g_gs0[e] = 0.f; g_gs1[e] = 0.f; }
    if (e < 2 * BB) g_cnt[e] = 0.f;
    if (e >= EE) return;
    int r = row[e];
    int idx = atomicAdd(&g_cursor[r], 1);
    int2 pk;
    pk.x = col[e];
    pk.y = __float_as_int(ea[e]);
    g_edge[idx] = pk;
}

// hop 0 fused (u==0): warp per node; lanes split edges for third term; emit bf16 u.
__global__ void k_hop0(const float* __restrict__ x,
                       const float* __restrict__ l3w, const float* __restrict__ l3b,
                       const float* __restrict__ l0w, const float* __restrict__ l0b,
                       const float* __restrict__ l1b,
                       const float* __restrict__ l2w, const float* __restrict__ l2b) {
    int warp = threadIdx.x >> 5, lane = threadIdx.x & 31;
    int n = blockIdx.x * 8 + warp;
    if (n >= NN) return;
    float w = l3w[0], b = l3b[0];
    int s = g_start[n], e = g_start[n + 1];
    float acc = 0.f;
    for (int t = s + lane; t < e; t += 32)
        acc += fmaxf(__int_as_float(g_edge[t].y) * w + b, 0.f);
    for (int o = 16; o; o >>= 1) acc += __shfl_xor_sync(0xffffffffu, acc, o);
    float third = (e > s) ? acc / (float)(e - s) : 0.f;
    float xv = x[n];
    int h0 = lane * 4;
    float v0 = xv * l0w[h0]     + third * l2w[h0]     + l0b[h0]     + l1b[h0]     + l2b[h0];
    float v1 = xv * l0w[h0 + 1] + third * l2w[h0 + 1] + l0b[h0 + 1] + l1b[h0 + 1] + l2b[h0 + 1];
    float v2 = xv * l0w[h0 + 2] + third * l2w[h0 + 2] + l0b[h0 + 2] + l1b[h0 + 2] + l2b[h0 + 2];
    float v3 = xv * l0w[h0 + 3] + third * l2w[h0 + 3] + l0b[h0 + 3] + l1b[h0 + 3] + l2b[h0 + 3];
    __nv_bfloat162 lo = __floats2bfloat162_rn(fmaxf(v0, 0.f), fmaxf(v1, 0.f));
    __nv_bfloat162 hi = __floats2bfloat162_rn(fmaxf(v2, 0.f), fmaxf(v3, 0.f));
    uint2 pk;
    pk.x = *reinterpret_cast<unsigned*>(&lo);
    pk.y = *reinterpret_cast<unsigned*>(&hi);
    reinterpret_cast<uint2*>(g_ub)[(size_t)n * 32 + lane] = pk;
}

// edge aggregation: 2 nodes per warp (16 lanes each, uint4 = 8 bf16 per lane).
// Packed edge stream; bf16 mean out; full-third per lane, hl==0 writes it.
__global__ void k_gather(const float* __restrict__ l3w, const float* __restrict__ l3b) {
    int warp = threadIdx.x >> 5, lane = threadIdx.x & 31;
    int hl = lane & 15;                      // lane within half-warp
    int n = blockIdx.x * 16 + warp * 2 + (lane >> 4);
    if (n >= NN) return;
    const uint4* ub4 = reinterpret_cast<const uint4*>(g_ub);  // 16 uint4 per node row
    float w = l3w[0], b = l3b[0];
    int s = g_start[n], e = g_start[n + 1];
    float a0x = 0.f, a1x = 0.f, a2x = 0.f, a3x = 0.f;
    float a4x = 0.f, a5x = 0.f, a6x = 0.f, a7x = 0.f;
    float tacc = 0.f;
    int t = s;
    for (; t + 3 < e; t += 4) {
        int2 e0 = g_edge[t],     e1 = g_edge[t + 1];
        int2 e2 = g_edge[t + 2], e3 = g_edge[t + 3];
        float c0 = __int_as_float(e0.y), c1 = __int_as_float(e1.y);
        float c2 = __int_as_float(e2.y), c3 = __int_as_float(e3.y);
        uint4 r0 = ub4[(size_t)e0.x * 16 + hl];
        uint4 r1 = ub4[(size_t)e1.x * 16 + hl];
        uint4 r2 = ub4[(size_t)e2.x * 16 + hl];
        uint4 r3 = ub4[(size_t)e3.x * 16 + hl];
        #define ACC8(R, C) { \
            float2 f0 = __bfloat1622float2(*reinterpret_cast<__nv_bfloat162*>(&R.x)); \
            float2 f1 = __bfloat1622float2(*reinterpret_cast<__nv_bfloat162*>(&R.y)); \
            float2 f2 = __bfloat1622float2(*reinterpret_cast<__nv_bfloat162*>(&R.z)); \
            float2 f3 = __bfloat1622float2(*reinterpret_cast<__nv_bfloat162*>(&R.w)); \
            a0x += C * f0.x; a1x += C * f0.y; a2x += C * f1.x; a3x += C * f1.y; \
            a4x += C * f2.x; a5x += C * f2.y; a6x += C * f3.x; a7x += C * f3.y; }
        ACC8(r0, c0) ACC8(r1, c1) ACC8(r2, c2) ACC8(r3, c3)
        tacc += fmaxf(c0 * w + b, 0.f) + fmaxf(c1 * w + b, 0.f)
              + fmaxf(c2 * w + b, 0.f) + fmaxf(c3 * w + b, 0.f);
    }
    for (; t < e; t++) {
        int2 e0 = g_edge[t];
        float c0 = __int_as_float(e0.y);
        uint4 r0 = ub4[(size_t)e0.x * 16 + hl];
        ACC8(r0, c0)
        tacc += fmaxf(c0 * w + b, 0.f);
    }
    #undef ACC8
    float inv = (e > s) ? 1.f / (float)(e - s) : 0.f;
    __nv_bfloat162 b0 = __floats2bfloat162_rn(a0x * inv, a1x * inv);
    __nv_bfloat162 b1 = __floats2bfloat162_rn(a2x * inv, a3x * inv);
    __nv_bfloat162 b2 = __floats2bfloat162_rn(a4x * inv, a5x * inv);
    __nv_bfloat162 b3 = __floats2bfloat162_rn(a6x * inv, a7x * inv);
    uint4 pk;
    pk.x = *reinterpret_cast<unsigned*>(&b0);
    pk.y = *reinterpret_cast<unsigned*>(&b1);
    pk.z = *reinterpret_cast<unsigned*>(&b2);
    pk.w = *reinterpret_cast<unsigned*>(&b3);
    reinterpret_cast<uint4*>(g_meanb)[(size_t)n * 16 + hl] = pk;
    if (hl == 0) g_third[n] = tacc * inv;
}

// bf16 tensor-core GEMM via mma.sync (base sm_103 ISA) + fused hop epilogue.
__global__ __launch_bounds__(256) void k_hmma(
    const float* __restrict__ x,
    const __nv_bfloat16* __restrict__ wtb,   // [128 c][128 k] bf16 row-major
    const float* __restrict__ l0w, const float* __restrict__ l2w,
    const float* __restrict__ b0, const float* __restrict__ b1,
    const float* __restrict__ b2) {
    extern __shared__ char smem[];
    uint32_t sbase = smem_u32(smem);
    int tid = threadIdx.x, lane = tid & 31, w = tid >> 5;
    int n0g = blockIdx.x * 128;

    for (int i = tid; i < 128 * 32; i += 256) {
        int row = i >> 5, u2 = i & 31;
        int n = n0g + row;
        uint2 v = (n < NN) ? g_meanb[(size_t)n * 32 + u2] : make_uint2(0u, 0u);
        *reinterpret_cast<uint2*>(smem + SH_A + row * (ASTB * 2) + u2 * 8) = v;
    }
    const uint2* wb = reinterpret_cast<const uint2*>(wtb);
    for (int i = tid; i < 128 * 32; i += 256) {
        int row = i >> 5, u2 = i & 31;
        *reinterpret_cast<uint2*>(smem + SH_B + row * (ASTB * 2) + u2 * 8) = wb[row * 32 + u2];
    }
    if (tid < 128) {
        reinterpret_cast<float*>(smem + SH_CB)[tid] = b0[tid] + b1[tid] + b2[tid];
        reinterpret_cast<float*>(smem + SH_C0)[tid] = l0w[tid];
        reinterpret_cast<float*>(smem + SH_C2)[tid] = l2w[tid];
    }
    __syncthreads();

    int lg = lane >> 3, li = lane & 7;
    int rowA = w * 16 + (lg & 1) * 8 + li;
    uint32_t aBase = sbase + SH_A + rowA * (ASTB * 2) + ((lg >> 1) * 8) * 2;
    int rowBb = (lg >> 1) * 8 + li;
    uint32_t bBase = sbase + SH_B + rowBb * (ASTB * 2) + ((lg & 1) * 8) * 2;

    float acc[16][4];
    #pragma unroll
    for (int t = 0; t < 16; t++)
        #pragma unroll
        for (int j = 0; j < 4; j++) acc[t][j] = 0.f;

    #pragma unroll 1
    for (int ks = 0; ks < 8; ks++) {
        uint32_t kb2 = ks * 32;
        uint32_t a0, a1, a2, a3;
        asm volatile("ldmatrix.sync.aligned.m8n8.x4.shared.b16 {%0,%1,%2,%3}, [%4];"
                     : "=r"(a0), "=r"(a1), "=r"(a2), "=r"(a3) : "r"(aBase + kb2));
        #pragma unroll
        for (int np = 0; np < 8; np++) {
            uint32_t r0, r1, r2, r3;
            asm volatile("ldmatrix.sync.aligned.m8n8.x4.shared.b16 {%0,%1,%2,%3}, [%4];"
                         : "=r"(r0), "=r"(r1), "=r"(r2), "=r"(r3)
                         : "r"(bBase + np * 16 * (ASTB * 2) + kb2));
            asm volatile(
                "mma.sync.aligned.m16n8k16.row.col.f32.bf16.bf16.f32 "
                "{%0,%1,%2,%3}, {%4,%5,%6,%7}, {%8,%9}, {%0,%1,%2,%3};"
                : "+f"(acc[2 * np][0]), "+f"(acc[2 * np][1]),
                  "+f"(acc[2 * np][2]), "+f"(acc[2 * np][3])
                : "r"(a0), "r"(a1), "r"(a2), "r"(a3), "r"(r0), "r"(r1));
            asm volatile(
                "mma.sync.aligned.m16n8k16.row.col.f32.bf16.bf16.f32 "
                "{%0,%1,%2,%3}, {%4,%5,%6,%7}, {%8,%9}, {%0,%1,%2,%3};"
                : "+f"(acc[2 * np + 1][0]), "+f"(acc[2 * np + 1][1]),
                  "+f"(acc[2 * np + 1][2]), "+f"(acc[2 * np + 1][3])
                : "r"(a0), "r"(a1), "r"(a2), "r"(a3), "r"(r2), "r"(r3));
        }
    }

    int q = lane & 3;
    int row0 = w * 16 + (lane >> 2), row1 = row0 + 8;
    int nA = n0g + row0, nB = n0g + row1;
    float xA = 0.f, tA = 0.f, xB = 0.f, tB = 0.f;
    if (nA < NN) { xA = x[nA]; tA = g_third[nA]; }
    if (nB < NN) { xB = x[nB]; tB = g_third[nB]; }
    const float* sCB = reinterpret_cast<const float*>(smem + SH_CB);
    const float* sC0 = reinterpret_cast<const float*>(smem + SH_C0);
    const float* sC2 = reinterpret_cast<const float*>(smem + SH_C2);

    #pragma unroll
    for (int t = 0; t < 16; t++) {
        int c = t * 8 + q * 2;
        float2 bb = *reinterpret_cast<const float2*>(&sCB[c]);
        float2 w0 = *reinterpret_cast<const float2*>(&sC0[c]);
        float2 w2 = *reinterpret_cast<const float2*>(&sC2[c]);
        float oA0 = fmaxf(xA * w0.x + tA * w2.x + bb.x + acc[t][0], 0.f);
        float oA1 = fmaxf(xA * w0.y + tA * w2.y + bb.y + acc[t][1], 0.f);
        float oB0 = fmaxf(xB * w0.x + tB * w2.x + bb.x + acc[t][2], 0.f);
        float oB1 = fmaxf(xB * w0.y + tB * w2.y + bb.y + acc[t][3], 0.f);
        if (nA < NN) g_ub[(size_t)nA * 64 + (c >> 1)] = __floats2bfloat162_rn(oA0, oA1);
        if (nB < NN) g_ub[(size_t)nB * 64 + (c >> 1)] = __floats2bfloat162_rn(oB0, oB1);
    }
}

// per-graph pooled sums (batch sorted -> register accumulate, flush on change)
// reads bf16 u; 782 blocks (parallelism matters here — r16 lesson)
__global__ void k_pool(const float* __restrict__ x, const int* __restrict__ batch) {
    int h = threadIdx.x;               // 128
    int n0 = blockIdx.x * 128;
    if (n0 >= NN) return;
    int n1 = n0 + 128; if (n1 > NN) n1 = NN;
    const __nv_bfloat16* ubh = reinterpret_cast<const __nv_bfloat16*>(g_ub);
    int gcur = batch[n0];
    float a0 = 0.f, a1 = 0.f, c0 = 0.f, c1 = 0.f;
    for (int n = n0; n < n1; n++) {
        int g = batch[n];
        if (g != gcur) {
            atomicAdd(&g_gs0[gcur * HH + h], a0);
            atomicAdd(&g_gs1[gcur * HH + h], a1);
            if (h == 0) { atomicAdd(&g_cnt[gcur], c0); atomicAdd(&g_cnt[BB + gcur], c1); }
            a0 = a1 = c0 = c1 = 0.f;
            gcur = g;
        }
        float xv = x[n];
        float uv = __bfloat162float(ubh[(size_t)n * HH + h]);
        a0 += uv * (1.f - xv); a1 += uv * xv;
        c0 += 1.f - xv;        c1 += xv;
    }
    atomicAdd(&g_gs0[gcur * HH + h], a0);
    atomicAdd(&g_gs1[gcur * HH + h], a1);
    if (h == 0) { atomicAdd(&g_cnt[gcur], c0); atomicAdd(&g_cnt[BB + gcur], c1); }
}

// per-graph: hc0/hc1, folded attention vectors v0/v1 = att_w @ hc, and 10 scalars
__global__ void k_graph(const float* __restrict__ attw, const float* __restrict__ attb) {
    __shared__ float hc0[HH], hc1[HH], v0[2 * HH], v1[2 * HH];
    int g = blockIdx.x, t = threadIdx.x;  // 256 threads
    if (t < HH) {
        float c0 = g_cnt[g], c1 = g_cnt[BB + g];
        hc0[t] = (c0 > 0.f) ? g_gs0[g * HH + t] / c0 : 0.f;
        hc1[t] = (c1 > 0.f) ? g_gs1[g * HH + t] / c1 : 0.f;
    }
    __syncthreads();
    {
        float s0 = 0.f, s1 = 0.f;
        const float* wrow = attw + t * HH;
        for (int j = 0; j < HH; j++) { float w = wrow[j]; s0 += w * hc0[j]; s1 += w * hc1[j]; }
        v0[t] = s0; v1[t] = s1;
        if (t < HH) { g_v0t[g * HH + t] = s0; g_v1t[g * HH + t] = s1; }
    }
    __syncthreads();
    int warp = t >> 5, lane = t & 31;
    for (int id = warp; id < 10; id += 8) {
        const float* vec; const float* hc;
        switch (id) {
            case 0: vec = attb;     hc = hc0; break;  // s0
            case 1: vec = attb;     hc = hc1; break;  // s1
            case 2: vec = g_spvec;  hc = hc0; break;  // p0
            case 3: vec = g_spvec;  hc = hc1; break;  // p1
            case 4: vec = g_acbot;  hc = hc0; break;  // a0
            case 5: vec = g_acbot;  hc = hc1; break;  // a1
            case 6: vec = v0 + HH;  hc = hc0; break;  // d00
            case 7: vec = v0 + HH;  hc = hc1; break;  // d01
            case 8: vec = v1 + HH;  hc = hc0; break;  // d10
            default: vec = v1 + HH; hc = hc1; break;  // d11
        }
        float s = 0.f;
        for (int j = lane; j < HH; j += 32) s += vec[j] * hc[j];
        for (int o = 16; o; o >>= 1) s += __shfl_down_sync(0xffffffffu, s, o);
        if (lane == 0) g_scal[g * 10 + id] = s;
    }
}

// per-node head: 3 dots of length 128 + softmax over 2 + folded output (bf16 u)
__global__ void k_final(const float* __restrict__ x, const int* __restrict__ batch,
                        float* __restrict__ out) {
    int warp = threadIdx.x >> 5, lane = threadIdx.x & 31;
    int n = blockIdx.x * 8 + warp;
    if (n >= NN) return;
    int g = batch[n];
    uint2 upk = reinterpret_cast<const uint2*>(g_ub)[(size_t)n * 32 + lane];
    float2 ulo = __bfloat1622float2(*reinterpret_cast<__nv_bfloat162*>(&upk.x));
    float2 uhi = __bfloat1622float2(*reinterpret_cast<__nv_bfloat162*>(&upk.y));
    float4 uv = make_float4(ulo.x, ulo.y, uhi.x, uhi.y);
    float4 vA = *reinterpret_cast<const float4*>(&g_v0t[g * HH + lane * 4]);
    float4 vB = *reinterpret_cast<const float4*>(&g_v1t[g * HH + lane * 4]);
    float4 vC = *reinterpret_cast<const float4*>(&g_actop[lane * 4]);
    float da = uv.x * vA.x + uv.y * vA.y + uv.z * vA.z + uv.w * vA.w;
    float db = uv.x * vB.x + uv.y * vB.y + uv.z * vB.z + uv.w * vB.w;
    float dc = uv.x * vC.x + uv.y * vC.y + uv.z * vC.z + uv.w * vC.w;
    for (int o = 16; o; o >>= 1) {
        da += __shfl_down_sync(0xffffffffu, da, o);
        db += __shfl_down_sync(0xffffffffu, db, o);
        dc += __shfl_down_sync(0xffffffffu, dc, o);
    }
    if (lane == 0) {
        const float* sc = &g_scal[g * 10];
        bool xb = x[n] > 0.5f;
        float w0 = da + (xb ? sc[6] : sc[7]) + sc[0];
        float w1 = db + (xb ? sc[8] : sc[9]) + sc[1];
        float m = fmaxf(w0, w1);
        float e0 = __expf(w0 - m), e1 = __expf(w1 - m);
        float sw = e0 / (e0 + e1);
        out[n] = sw * sc[2] + (1.f - sw) * sc[3] + dc + (xb ? sc[4] : sc[5]) + g_c0;
    }
}

// ---------------- launch ----------------
extern "C" void kernel_launch(void* const* d_in, const int* in_sizes, int n_in,
                              void* d_out, int out_size) {
    int base = (n_in >= 21) ? 5 : 4;
    const float* x     = (const float*)d_in[0];
    const int*   ei    = (const int*)d_in[1];
    const float* ea    = (const float*)d_in[2];
    const int*   batch = (const int*)d_in[3];
    const float* l0w   = (const float*)d_in[base + 0];
    const float* l0b   = (const float*)d_in[base + 1];
    const float* l1w   = (const float*)d_in[base + 2];
    const float* l1b   = (const float*)d_in[base + 3];
    const float* l2w   = (const float*)d_in[base + 4];
    const float* l2b   = (const float*)d_in[base + 5];
    const float* l3w   = (const float*)d_in[base + 6];
    const float* l3b   = (const float*)d_in[base + 7];
    const float* attw  = (const float*)d_in[base + 8];
    const float* attb  = (const float*)d_in[base + 9];
    const float* spw   = (const float*)d_in[base + 10];
    const float* spb   = (const float*)d_in[base + 11];
    const float* acw   = (const float*)d_in[base + 12];
    const float* acb   = (const float*)d_in[base + 13];
    const float* lastw = (const float*)d_in[base + 14];
    const float* lastb = (const float*)d_in[base + 15];
    const int* row = ei;
    const int* col = ei + EE;
    float* out = (float*)d_out;

    static __nv_bfloat16* wtb_dev = nullptr;
    if (!wtb_dev) cudaGetSymbolAddress((void**)&wtb_dev, g_wtb);

    cudaFuncSetAttribute(k_hmma, cudaFuncAttributeMaxDynamicSharedMemorySize, SH_TOTAL);

    k_hist<<<(EE + 255) / 256, 256>>>(row, l1w, spw, spb, acw, acb, lastw, lastb);
    k_scan1<<<NB1, 256>>>();
    k_scan3<<<NB1, 256>>>();
    k_fill<<<(EE + 255) / 256, 256>>>(row, col, ea);

    // hop 0 (u == 0): fused third+update, bf16 out
    k_hop0<<<(NN + 7) / 8, 256>>>(x, l3w, l3b, l0w, l0b, l1b, l2w, l2b);

    // hops 1, 2: gather then tensor-core GEMM (bf16 u out)
    for (int i = 1; i < 3; i++) {
        k_gather<<<(NN + 15) / 16, 256>>>(l3w + i, l3b + i);
        k_hmma<<<(NN + 127) / 128, 256, SH_TOTAL>>>(
            x, wtb_dev + (i - 1) * HH * HH,
            l0w + i * HH, l2w + i * HH,
            l0b + i * HH, l1b + i * HH, l2b + i * HH);
    }

    k_pool<<<(NN + 127) / 128, 128>>>(x, batch);
    k_graph<<<BB, 256>>>(attw, attb);
    k_final<<<NN / 8, 256>>>(x, batch, out);
}